// round 1
// baseline (speedup 1.0000x reference)
#include <cuda_runtime.h>

// Problem constants (fixed by the reference):
//   image 1000x1000, patch 5x5 -> 200x200 = 40000 patches
//   coefficients [40000, 3, 10, 2], bias [40000, 3]
//   out [3, 1000000]
#define IMG_W          1000
#define NUM_PIX        1000000
#define PATCH          5
#define PATCHES_PER_ROW 200
#define NTERMS         10
#define COEF_PER_PATCH 60          // 3*10*2
#define PB             40          // patches per block (one fifth of a patch-row)
#define NTHREADS       256         // 200 compute threads + spare for copies
#define SM_STRIDE      68          // 60 padded to 68 floats: conflict-free LDS.128

__global__ __launch_bounds__(NTHREADS, 2)
void ts_kernel(const float* __restrict__ pix,
               const float* __restrict__ coef,
               const float* __restrict__ bias,
               float* __restrict__ out)
{
    __shared__ float sc[PB * SM_STRIDE];            // 40*68*4   = 10880 B
    __shared__ float sb[PB * 3];                    //             480 B
    __shared__ float so[3 * PATCH * (PB * PATCH)];  // 3*5*200*4 = 12000 B

    const int tid = threadIdx.x;
    const int b   = blockIdx.x;          // 0..999
    const int pr  = b / 5;               // patch row 0..199
    const int cb  = (b - pr * 5) * PB;   // patch-col base: 0,40,80,120,160
    const int pbase = pr * PATCHES_PER_ROW + cb;

    // ---- Phase 1: cooperative coefficient + bias load (fully coalesced) ----
    // 40 patches * 60 floats = 2400 floats = 600 float4, contiguous in gmem.
    {
        const float4* g4 = (const float4*)(coef + (size_t)pbase * COEF_PER_PATCH);
        #pragma unroll
        for (int k = 0; k < 3; k++) {
            int idx = tid + k * NTHREADS;
            if (idx < 600) {
                float4 v = g4[idx];
                int pp  = idx / 15;        // 15 float4 per patch
                int off = idx - pp * 15;
                *(float4*)&sc[pp * SM_STRIDE + off * 4] = v;
            }
        }
        if (tid < PB * 3) sb[tid] = bias[(size_t)pbase * 3 + tid];
    }
    __syncthreads();

    // ---- Phase 2: compute (200 threads; thread = 5-pixel segment of one patch) ----
    if (tid < PB * PATCH) {
        const int p_local = tid % PB;        // 0..39
        const int seg     = tid / PB;        // 0..4 (pixel row within patch)
        const int row     = pr * PATCH + seg;
        const int colBase = (cb + p_local) * PATCH;
        const int pixBase = row * IMG_W + colBase;

        // Pull this patch's 60 coefficients into registers (15 LDS.128, conflict-free)
        float c[COEF_PER_PATCH];
        #pragma unroll
        for (int j = 0; j < 15; j++) {
            float4 v = *(const float4*)&sc[p_local * SM_STRIDE + j * 4];
            c[4 * j + 0] = v.x;
            c[4 * j + 1] = v.y;
            c[4 * j + 2] = v.z;
            c[4 * j + 3] = v.w;
        }
        const float b0 = sb[p_local * 3 + 0];
        const float b1 = sb[p_local * 3 + 1];
        const float b2 = sb[p_local * 3 + 2];

        #pragma unroll
        for (int i = 0; i < PATCH; i++) {
            const int n = pixBase + i;
            const float2 xy = *(const float2*)&pix[2 * (size_t)n];
            const float x = xy.x, y = xy.y;

            #pragma unroll
            for (int ch = 0; ch < 3; ch++) {
                // Horner over t for x-chain and y-chain
                float rx = c[ch * 20 + 9 * 2 + 0];
                float ry = c[ch * 20 + 9 * 2 + 1];
                #pragma unroll
                for (int t = 8; t >= 0; t--) {
                    rx = fmaf(rx, x, c[ch * 20 + t * 2 + 0]);
                    ry = fmaf(ry, y, c[ch * 20 + t * 2 + 1]);
                }
                const float bv = (ch == 0) ? b0 : ((ch == 1) ? b1 : b2);
                // stage into smem: so[ch][seg][p_local*5 + i]  (5 coprime 32 -> no conflicts)
                so[(ch * PATCH + seg) * (PB * PATCH) + p_local * PATCH + i] = rx + ry + bv;
            }
        }
    }
    __syncthreads();

    // ---- Phase 3: coalesced float4 output copy ----
    // 3*5*200 = 3000 floats = 750 float4. Each (ch,seg) row is 200 contiguous
    // floats mapping to a contiguous gmem run (cb*5 is a multiple of 200 -> 16B aligned).
    {
        const float4* s4 = (const float4*)so;
        #pragma unroll
        for (int k = 0; k < 3; k++) {
            int j = tid + k * NTHREADS;
            if (j < 750) {
                int chseg = j / 50;           // 50 float4 per (ch,seg) row
                int off   = j - chseg * 50;
                int ch    = chseg / PATCH;
                int seg   = chseg - ch * PATCH;
                int gfl   = ch * NUM_PIX + (pr * PATCH + seg) * IMG_W + cb * PATCH + off * 4;
                *(float4*)&out[gfl] = s4[j];
            }
        }
    }
}

extern "C" void kernel_launch(void* const* d_in, const int* in_sizes, int n_in,
                              void* d_out, int out_size)
{
    const float* pix  = (const float*)d_in[0];   // [1000000, 2]
    const float* coef = (const float*)d_in[1];   // [40000, 3, 10, 2]
    const float* bias = (const float*)d_in[2];   // [40000, 3]
    float* out = (float*)d_out;                  // [3, 1000000]

    (void)in_sizes; (void)n_in; (void)out_size;
    ts_kernel<<<1000, NTHREADS>>>(pix, coef, bias, out);
}

// round 2
// speedup vs baseline: 1.0745x; 1.0745x over previous
#include <cuda_runtime.h>

// Problem constants (fixed by the reference):
//   image 1000x1000, patch 5x5 -> 200x200 = 40000 patches
//   coefficients [40000, 3, 10, 2], bias [40000, 3]
//   out [3, 1000000]
#define IMG_W           1000
#define NUM_PIX         1000000
#define PATCH           5
#define PATCHES_PER_ROW 200
#define COEF_PER_PATCH  60          // 3*10*2
#define PB              40          // patches per block (one fifth of a patch-row)
#define NTHREADS        256         // 200 compute threads + spare for copies
#define SM_STRIDE       68          // 60 padded to 68 floats: conflict-free LDS.128

__global__ __launch_bounds__(NTHREADS, 4)
void ts_kernel(const float* __restrict__ pix,
               const float* __restrict__ coef,
               const float* __restrict__ bias,
               float* __restrict__ out)
{
    __shared__ float sc[PB * SM_STRIDE];            // 40*68*4   = 10880 B
    __shared__ float sb[PB * 3];                    //             480 B
    __shared__ float so[3 * PATCH * (PB * PATCH)];  // 3*5*200*4 = 12000 B

    const int tid = threadIdx.x;
    const int b   = blockIdx.x;          // 0..999
    const int pr  = b / 5;               // patch row 0..199
    const int cb  = (b - pr * 5) * PB;   // patch-col base: 0,40,80,120,160
    const int pbase = pr * PATCHES_PER_ROW + cb;

    // ---- Phase 1: cooperative coefficient + bias load (fully coalesced) ----
    // 40 patches * 60 floats = 2400 floats = 600 float4, contiguous in gmem.
    {
        const float4* g4 = (const float4*)(coef + (size_t)pbase * COEF_PER_PATCH);
        #pragma unroll
        for (int k = 0; k < 3; k++) {
            int idx = tid + k * NTHREADS;
            if (idx < 600) {
                float4 v = g4[idx];
                int pp  = idx / 15;        // 15 float4 per patch
                int off = idx - pp * 15;
                *(float4*)&sc[pp * SM_STRIDE + off * 4] = v;
            }
        }
        if (tid < PB * 3) sb[tid] = bias[(size_t)pbase * 3 + tid];
    }
    __syncthreads();

    // ---- Phase 2: compute (200 threads; thread = 5-pixel segment of one patch) ----
    // Channel-major, 5-wide pixel accumulators: each float4 coefficient load
    // (two (cx,cy) pairs) feeds 20 FMAs. ~40 live regs -> fully register-resident.
    if (tid < PB * PATCH) {
        const int p_local = tid % PB;        // 0..39
        const int seg     = tid / PB;        // 0..4 (pixel row within patch)
        const int row     = pr * PATCH + seg;
        const int pixBase = row * IMG_W + (cb + p_local) * PATCH;

        float x[PATCH], y[PATCH];
        #pragma unroll
        for (int i = 0; i < PATCH; i++) {
            const float2 xy = *(const float2*)&pix[2 * (size_t)(pixBase + i)];
            x[i] = xy.x; y[i] = xy.y;
        }

        const float* cc0 = &sc[p_local * SM_STRIDE];

        #pragma unroll
        for (int ch = 0; ch < 3; ch++) {
            const float* cc = cc0 + ch * 20;   // [t*2+d], t=0..9, d in {x,y}
            const float bv = sb[p_local * 3 + ch];

            float rx[PATCH], ry[PATCH];
            // top float4: (cx8, cy8, cx9, cy9)
            {
                float4 v = *(const float4*)(cc + 16);
                #pragma unroll
                for (int i = 0; i < PATCH; i++) {
                    rx[i] = fmaf(v.z, x[i], v.x);   // t=9 -> t=8
                    ry[i] = fmaf(v.w, y[i], v.y);
                }
            }
            #pragma unroll
            for (int j = 3; j >= 0; j--) {
                float4 v = *(const float4*)(cc + j * 4);  // (cx_2j, cy_2j, cx_2j+1, cy_2j+1)
                #pragma unroll
                for (int i = 0; i < PATCH; i++) {
                    rx[i] = fmaf(rx[i], x[i], v.z);       // t = 2j+1
                    ry[i] = fmaf(ry[i], y[i], v.w);
                }
                #pragma unroll
                for (int i = 0; i < PATCH; i++) {
                    rx[i] = fmaf(rx[i], x[i], v.x);       // t = 2j
                    ry[i] = fmaf(ry[i], y[i], v.y);
                }
            }
            // stage into smem: so[ch][seg][p_local*5 + i] (5 coprime 32 -> no conflicts)
            float* dst = &so[(ch * PATCH + seg) * (PB * PATCH) + p_local * PATCH];
            #pragma unroll
            for (int i = 0; i < PATCH; i++)
                dst[i] = rx[i] + ry[i] + bv;
        }
    }
    __syncthreads();

    // ---- Phase 3: coalesced float4 output copy ----
    // 3*5*200 = 3000 floats = 750 float4; each (ch,seg) row is a contiguous
    // 200-float run in gmem (cb*5 multiple of 200 -> 16B aligned).
    {
        const float4* s4 = (const float4*)so;
        #pragma unroll
        for (int k = 0; k < 3; k++) {
            int j = tid + k * NTHREADS;
            if (j < 750) {
                int chseg = j / 50;           // 50 float4 per (ch,seg) row
                int off   = j - chseg * 50;
                int ch    = chseg / PATCH;
                int seg   = chseg - ch * PATCH;
                int gfl   = ch * NUM_PIX + (pr * PATCH + seg) * IMG_W + cb * PATCH + off * 4;
                *(float4*)&out[gfl] = s4[j];
            }
        }
    }
}

extern "C" void kernel_launch(void* const* d_in, const int* in_sizes, int n_in,
                              void* d_out, int out_size)
{
    const float* pix  = (const float*)d_in[0];   // [1000000, 2]
    const float* coef = (const float*)d_in[1];   // [40000, 3, 10, 2]
    const float* bias = (const float*)d_in[2];   // [40000, 3]
    float* out = (float*)d_out;                  // [3, 1000000]

    (void)in_sizes; (void)n_in; (void)out_size;
    ts_kernel<<<1000, NTHREADS>>>(pix, coef, bias, out);
}